// round 16
// baseline (speedup 1.0000x reference)
#include <cuda_runtime.h>
#include <cuda_fp16.h>
#include <math.h>
#include <float.h>
#include <stdint.h>

static constexpr int S = 1024;
static constexpr int Bd = 2;
static constexpr int D = 1024;
static constexpr int H = 16;
static constexpr int DEPTH = 64;
static constexpr int DFF = 4096;
static constexpr int R = S * Bd;
static constexpr int BH = Bd * H;
static constexpr float SCALE = 0.125f;
static constexpr float NEGV = -1000000000.0f;
static constexpr float EPSV = 1e-5f;

// ------------------- scratch -------------------------------------------------
__device__ float g_attn[R * D];      // only fallback rows ever written/read
__device__ float g_h1[R * D];
__device__ float g_ffn[2 * R * D];   // split-K partials (z = 0,1)
__device__ float2 g_wqk[D * H];      // interleaved (wqsum, wksum)
__device__ float g_qsT[BH * S];
__device__ float g_ktsT[BH * S];
__device__ float2 g_pk[BH * S];      // (kts, kts + NEG*min(m,64))
__device__ float g_A2[BH * S];
__device__ float g_P1[BH * S];
__device__ float g_SA1[BH];
__device__ float g_mx[BH];
__device__ float g_mn[BH];
__device__ float g_mx2[BH];
__device__ float g_mn2[BH];
__device__ int   g_kmx[BH];
__device__ int   g_kmn[BH];
__device__ float g_Vsel[BH * 2 * DEPTH];
// fp16 operands
__device__ __half g_h1h[R * D];
__device__ __half g_midh[R * DFF];
__device__ __half g_W1T[DFF * D];
__device__ __half g_W2T[D * DFF];

// ------------------- PTX helpers ---------------------------------------------
__device__ __forceinline__ uint32_t smem_to_u32(const void* p) {
    uint32_t a;
    asm("{ .reg .u64 t; cvta.to.shared.u64 t, %1; cvt.u32.u64 %0, t; }" : "=r"(a) : "l"(p));
    return a;
}
__device__ __forceinline__ void ldsm4(uint32_t* r, uint32_t addr) {
    asm volatile("ldmatrix.sync.aligned.m8n8.x4.shared.b16 {%0,%1,%2,%3}, [%4];"
        : "=r"(r[0]), "=r"(r[1]), "=r"(r[2]), "=r"(r[3]) : "r"(addr));
}
__device__ __forceinline__ void mma16816(float* d, const uint32_t* a, const uint32_t* b) {
    asm volatile(
        "mma.sync.aligned.m16n8k16.row.col.f32.f16.f16.f32 "
        "{%0,%1,%2,%3}, {%4,%5,%6,%7}, {%8,%9}, {%0,%1,%2,%3};"
        : "+f"(d[0]), "+f"(d[1]), "+f"(d[2]), "+f"(d[3])
        : "r"(a[0]), "r"(a[1]), "r"(a[2]), "r"(a[3]), "r"(b[0]), "r"(b[1]));
}
__device__ __forceinline__ void cpasync16(uint32_t saddr, const void* gaddr) {
    asm volatile("cp.async.cg.shared.global [%0], [%1], 16;" :: "r"(saddr), "l"(gaddr));
}
#define CP_COMMIT() asm volatile("cp.async.commit_group;" ::: "memory")
#define CP_WAIT3()  asm volatile("cp.async.wait_group 3;" ::: "memory")
#define CP_WAIT2()  asm volatile("cp.async.wait_group 2;" ::: "memory")
#define CP_WAIT1()  asm volatile("cp.async.wait_group 1;" ::: "memory")
#define CP_WAIT0()  asm volatile("cp.async.wait_group 0;" ::: "memory")

// ------------------- K0: interleaved column-group sums of Wq, Wk -------------
__global__ void k_wsum(const float* __restrict__ wq, const float* __restrict__ wk) {
    int idx = blockIdx.x * blockDim.x + threadIdx.x;
    if (idx >= D * H) return;
    int k = idx / H, h = idx % H;
    const float* p1 = wq + (size_t)k * D + h * DEPTH;
    const float* p2 = wk + (size_t)k * D + h * DEPTH;
    float s1 = 0.f, s2 = 0.f;
#pragma unroll 16
    for (int d = 0; d < DEPTH; d++) { s1 += p1[d]; s2 += p2[d]; }
    g_wqk[k * H + h] = make_float2(s1, s2);
}

// ------------------- K1: qs / kts (+ packed pk write) -------------------------
__global__ void k_qskts(const float* __restrict__ x) {
    int r = blockIdx.x;
    int t = threadIdx.x;
    __shared__ float sx[D];
    {
        float4 v = ((const float4*)(x + (size_t)r * D))[t];
        *(float4*)(sx + t * 4) = v;
    }
    __syncthreads();
    int h = t & 15, part = t >> 4;
    float a1 = 0.f, a2 = 0.f;
#pragma unroll 8
    for (int k = part; k < D; k += 16) {
        float xv = sx[k];
        float2 w = g_wqk[k * H + h];
        a1 = fmaf(xv, w.x, a1);
        a2 = fmaf(xv, w.y, a2);
    }
    __shared__ float s1[16][16];
    __shared__ float s2[16][16];
    s1[part][h] = a1; s2[part][h] = a2;
    __syncthreads();
    if (t < H) {
        float q = 0.f, kk = 0.f;
#pragma unroll
        for (int p = 0; p < 16; p++) { q += s1[p][t]; kk += s2[p][t]; }
        int b = r >> 10, s = r & 1023;
        int o = (b * H + t) * S + s;
        g_qsT[o]  = SCALE * q;
        g_ktsT[o] = kk;
        g_pk[o] = make_float2(kk, kk + NEGV * (float)min(s, 64));
    }
}

// ------------------- transpose: W[Kd][Nd] -> WT fp16 [Nd][Kd] -----------------
__global__ void k_trsp(const float* __restrict__ W, __half* __restrict__ T,
                       int Kd, int Nd) {
    __shared__ float tile[32][33];
    int n0 = blockIdx.x * 32, k0 = blockIdx.y * 32;
    int c = threadIdx.x & 31, rq = threadIdx.x >> 5;
#pragma unroll
    for (int q = 0; q < 4; q++) {
        int kr = rq + q * 8;
        tile[kr][c] = W[(size_t)(k0 + kr) * Nd + n0 + c];
    }
    __syncthreads();
#pragma unroll
    for (int q = 0; q < 4; q++) {
        int nr = rq + q * 8;
        T[(size_t)(n0 + nr) * Kd + k0 + c] = __float2half_rn(tile[c][nr]);
    }
}

// ------------------- single-pass fp16 GEMM via mma.sync -----------------------
static constexpr int ROWB = 80;
static constexpr int TILEB = 128 * ROWB;
static constexpr int BUFB = 2 * TILEB;
static constexpr int NSTAGE = 4;
static constexpr int GEMM_SMEM = NSTAGE * BUFB;

template <int EPI>   // 1: bias+relu -> Ch fp16 ; 3: split-K partial -> fp32
__global__ void __launch_bounds__(256, 2)
mma_gemm(const __half* __restrict__ A, const __half* __restrict__ B,
         const float* __restrict__ bias, float* __restrict__ C,
         __half* __restrict__ Ch,
         int M, int N, int Ktot, int Ksl) {
    extern __shared__ char smem[];
    const uint32_t sbase = smem_to_u32(smem);
    int t = threadIdx.x;
    int lane = t & 31, wid = t >> 5;
    int wm = wid >> 2, wn = wid & 3;
    int m0 = blockIdx.y * 128, n0 = blockIdx.x * 128;
    const int kbase = blockIdx.z * Ksl;

    int lr = t >> 1, lh = t & 1;
    const __half* gsrc[2] = {
        A + (size_t)(m0 + lr) * Ktot + kbase + lh * 16,
        B + (size_t)(n0 + lr) * Ktot + kbase + lh * 16 };
    const uint32_t sdst = sbase + (uint32_t)(lr * ROWB + lh * 32);

    uint32_t aoff = (uint32_t)((wm * 64 + ((lane >> 3) & 1) * 8 + (lane & 7)) * ROWB
                               + ((lane >> 4) & 1) * 16);
    uint32_t boff = (uint32_t)((wn * 32 + ((lane >> 4) & 1) * 8 + (lane & 7)) * ROWB
                               + ((lane >> 3) & 1) * 16);

    float acc[4][4][4];
#pragma unroll
    for (int i = 0; i < 4; i++)
#pragma unroll
        for (int j = 0; j < 4; j++)
#pragma unroll
            for (int e = 0; e < 4; e++) acc[i][j][e] = 0.f;

#define ISSUE(chunk, buf) do { \
    uint32_t _db = sdst + (uint32_t)(buf) * BUFB; \
    size_t _go = (size_t)(chunk) * 32; \
    _Pragma("unroll") \
    for (int _tl = 0; _tl < 2; _tl++) { \
        const __half* _g = gsrc[_tl] + _go; \
        cpasync16(_db + _tl * TILEB,      _g); \
        cpasync16(_db + _tl * TILEB + 16, _g + 8); \
    } } while (0)

    const int NC = Ksl >> 5;
    ISSUE(0, 0); CP_COMMIT();
    ISSUE(1, 1); CP_COMMIT();
    ISSUE(2, 2); CP_COMMIT();

    int buf = 0;
    for (int c = 0; c < NC; c++) {
        if (c + 3 < NC) {
            int nb = buf + 3; if (nb >= NSTAGE) nb -= NSTAGE;
            ISSUE(c + 3, nb); CP_COMMIT(); CP_WAIT3();
        } else if (c + 2 < NC) {
            CP_WAIT2();
        } else if (c + 1 < NC) {
            CP_WAIT1();
        } else {
            CP_WAIT0();
        }
        __syncthreads();
        uint32_t bb = sbase + (uint32_t)buf * BUFB;
#pragma unroll
        for (int s = 0; s < 2; s++) {
            uint32_t Ah[4][4], Bh[2][4];
#pragma unroll
            for (int i = 0; i < 4; i++)
                ldsm4(Ah[i], bb + aoff + i * 16 * ROWB + s * 32);
#pragma unroll
            for (int j2 = 0; j2 < 2; j2++)
                ldsm4(Bh[j2], bb + TILEB + boff + j2 * 16 * ROWB + s * 32);
#pragma unroll
            for (int i = 0; i < 4; i++)
#pragma unroll
                for (int j = 0; j < 4; j++)
                    mma16816(acc[i][j], Ah[i], &Bh[j >> 1][(j & 1) * 2]);
        }
        __syncthreads();
        if (++buf == NSTAGE) buf = 0;
    }
#undef ISSUE

    int r0 = lane >> 2, c2 = (lane & 3) * 2;
    float* Cz = C;
    if constexpr (EPI == 3) Cz = C + (size_t)blockIdx.z * M * N;
#pragma unroll
    for (int i = 0; i < 4; i++) {
#pragma unroll
        for (int j = 0; j < 4; j++) {
            int m = m0 + wm * 64 + i * 16 + r0;
            int n = n0 + wn * 32 + j * 8 + c2;
            float v0 = acc[i][j][0], v1 = acc[i][j][1];
            float v2 = acc[i][j][2], v3 = acc[i][j][3];
            if constexpr (EPI == 1) {
                float b0 = bias[n], b1 = bias[n + 1];
                v0 = fmaxf(v0 + b0, 0.f); v1 = fmaxf(v1 + b1, 0.f);
                v2 = fmaxf(v2 + b0, 0.f); v3 = fmaxf(v3 + b1, 0.f);
                *(__half2*)(Ch + (size_t)m * N + n)       = __floats2half2_rn(v0, v1);
                *(__half2*)(Ch + (size_t)(m + 8) * N + n) = __floats2half2_rn(v2, v3);
            } else {
                *(float2*)(Cz + (size_t)m * N + n)       = make_float2(v0, v1);
                *(float2*)(Cz + (size_t)(m + 8) * N + n) = make_float2(v2, v3);
            }
        }
    }
}

// ------------------- K3: rel_w reductions (packed pk, float4) -----------------
__global__ void k_relw(const float* __restrict__ rel) {
    int p = blockIdx.x;
    int bh = blockIdx.y;
    int t = threadIdx.x;
    const float2* pk = g_pk + bh * S;
    int ks[2] = { p, 1023 - p };
    float res[4];
#pragma unroll
    for (int rr = 0; rr < 2; rr++) {
        int k = ks[rr];
        const float* base = rel + ((size_t)bh * S + k) * S + (1023 - k);
        int len = k + 1;
        int head = (4 - ((1023 - k) & 3)) & 3;
        if (head > len) head = len;
        float a1 = 0.f, a2 = 0.f;
        if (t < head) {
            float rv = base[t];
            float2 pv = pk[t];
            a1 += pv.x * rv;
            a2 += pv.y * rv;
        }
        int nvec = (len - head) >> 2;
        for (int i = t; i < nvec; i += 256) {
            int m0 = head + i * 4;
            float4 rv = *(const float4*)(base + m0);
            float2 p0 = pk[m0], p1 = pk[m0 + 1], p2 = pk[m0 + 2], p3 = pk[m0 + 3];
            a1 += p0.x * rv.x + p1.x * rv.y + p2.x * rv.z + p3.x * rv.w;
            a2 += p0.y * rv.x + p1.y * rv.y + p2.y * rv.z + p3.y * rv.w;
        }
        for (int m = head + nvec * 4 + t; m < len; m += 256) {
            float rv = base[m];
            float2 pv = pk[m];
            a1 += pv.x * rv;
            a2 += pv.y * rv;
        }
        res[rr * 2] = a1; res[rr * 2 + 1] = a2;
    }
    __shared__ float4 red[256];
    red[t] = make_float4(res[0], res[1], res[2], res[3]);
    __syncthreads();
    for (int o = 128; o > 0; o >>= 1) {
        if (t < o) {
            float4 a = red[t], b = red[t + o];
            red[t] = make_float4(a.x + b.x, a.y + b.y, a.z + b.z, a.w + b.w);
        }
        __syncthreads();
    }
    if (t == 0) {
        float4 v = red[0];
        g_P1[bh * S + ks[0]] = v.x;
        g_A2[bh * S + ks[0]] = v.y;
        g_P1[bh * S + ks[1]] = v.z;
        g_A2[bh * S + ks[1]] = v.w;
    }
}

// ------------------- K4: SA1 + top-2 extremes per bh -------------------------
__global__ void k_finalize() {
    int bh = blockIdx.x, t = threadIdx.x;
    __shared__ float ss[256];
    __shared__ float sv[256];
    __shared__ int   si[256];
    __shared__ float sw_[256];
    __shared__ int   sj[256];
    const float* A2 = g_A2 + bh * S;
    float sa = 0.f, mx = -FLT_MAX, mn = FLT_MAX;
    int im = 0, imn = 0;
    for (int k = t; k < S; k += 256) {
        sa += g_P1[bh * S + k];
        float a = A2[k];
        if (a > mx) { mx = a; im = k; }
        if (a < mn) { mn = a; imn = k; }
    }
    ss[t] = sa; sv[t] = mx; si[t] = im; sw_[t] = mn; sj[t] = imn;
    __syncthreads();
    for (int o = 128; o > 0; o >>= 1) {
        if (t < o) {
            ss[t] += ss[t + o];
            if (sv[t + o] > sv[t]) { sv[t] = sv[t + o]; si[t] = si[t + o]; }
            if (sw_[t + o] < sw_[t]) { sw_[t] = sw_[t + o]; sj[t] = sj[t + o]; }
        }
        __syncthreads();
    }
    int kmx = si[0], kmn = sj[0];
    float vmx = sv[0], vmn = sw_[0], vsa = ss[0];
    __syncthreads();
    float mx2 = -FLT_MAX, mn2 = FLT_MAX;
    for (int k = t; k < S; k += 256) {
        float a = A2[k];
        if (k != kmx && a > mx2) mx2 = a;
        if (k != kmn && a < mn2) mn2 = a;
    }
    sv[t] = mx2; sw_[t] = mn2;
    __syncthreads();
    for (int o = 128; o > 0; o >>= 1) {
        if (t < o) { sv[t] = fmaxf(sv[t], sv[t + o]); sw_[t] = fminf(sw_[t], sw_[t + o]); }
        __syncthreads();
    }
    if (t == 0) {
        g_SA1[bh] = vsa;
        g_mx[bh] = vmx; g_mn[bh] = vmn;
        g_mx2[bh] = sv[0]; g_mn2[bh] = sw_[0];
        g_kmx[bh] = kmx; g_kmn[bh] = kmn;
    }
}

// ------------------- K4b: compute ONLY the V rows the gather needs -----------
__global__ void k_vsel(const float* __restrict__ x, const float* __restrict__ wv) {
    int sel = blockIdx.x;
    int bh = blockIdx.y;
    int b = bh >> 4, h = bh & 15;
    int krow = sel ? g_kmn[bh] : g_kmx[bh];
    int t = threadIdx.x;
    int n = t & 63, part = t >> 6;
    const float* xr = x + ((size_t)b * S + krow) * D;
    const float* wc = wv + (size_t)h * DEPTH + n;
    float s = 0.f;
    for (int k = part * 256; k < part * 256 + 256; k++)
        s = fmaf(xr[k], wc[(size_t)k * D], s);
    __shared__ float red[4][64];
    red[part][n] = s;
    __syncthreads();
    if (t < 64)
        g_Vsel[(bh * 2 + sel) * DEPTH + t] =
            red[0][t] + red[1][t] + red[2][t] + red[3][t];
}

// ------------------- sel decision ---------------------------------------------
__device__ __forceinline__ int attn_sel(int bh, int j, float& cj_out) {
    float cj = SCALE * g_qsT[bh * S + j] * g_SA1[bh];
    cj_out = cj;
    if (cj > 0.f      && cj * (g_mx[bh] - g_mx2[bh]) > 90.f)    return 0;
    if (cj < 0.f && (-cj) * (g_mn2[bh] - g_mn[bh]) > 90.f)      return 1;
    return -1;
}

// ------------------- K5b: exact softmax fallback (16-row scan, early exit) ----
__global__ void __launch_bounds__(64)
k_attn_fb(const float* __restrict__ x, const float* __restrict__ wv) {
    int bh = blockIdx.y;
    int b = bh >> 4, h = bh & 15;
    int lane = threadIdx.x;
    for (int jj = 0; jj < 16; jj++) {
        int j = blockIdx.x * 16 + jj;
        float cj;
        if (attn_sel(bh, j, cj) >= 0) continue;
        float mj = (cj >= 0.f) ? cj * g_mx[bh] : cj * g_mn[bh];
        const float* A2 = g_A2 + bh * S;
        float den = 0.f, acc = 0.f;
        for (int k = 0; k < S; k++) {
            float e = __expf(fminf(cj * A2[k] - mj, 0.f));
            den += e;
            if (e > 0.f) {
                const float* xr = x + ((size_t)b * S + k) * D;
                const float* w = wv + (size_t)h * DEPTH + lane;
                float vv = 0.f;
                for (int kk = 0; kk < D; kk++)
                    vv = fmaf(xr[kk], w[(size_t)kk * D], vv);
                acc = fmaf(e, vv, acc);
            }
        }
        g_attn[((size_t)bh * S + j) * DEPTH + lane] = acc / den;
    }
}

// ------------------- LN kernels ------------------------------------------------
__global__ void __launch_bounds__(256)
k_ln1(const float* __restrict__ xa,
      const float* __restrict__ gam, const float* __restrict__ bet,
      float* __restrict__ out, __half* __restrict__ oh) {
    int r = blockIdx.x, t = threadIdx.x;
    int c = t * 4;
    int bh = r >> 6;
    int j = (r & 63) * 16 + (c >> 6);
    int n = c & 63;
    float cj;
    int sel = attn_sel(bh, j, cj);
    float4 av;
    if (sel >= 0) av = *(const float4*)(g_Vsel + (bh * 2 + sel) * DEPTH + n);
    else          av = *(const float4*)(g_attn + (size_t)r * D + c);

    float4 xv = *(const float4*)(xa + (size_t)r * D + c);
    float v0 = xv.x + av.x, v1 = xv.y + av.y, v2 = xv.z + av.z, v3 = xv.w + av.w;

    __shared__ float red[256];
    red[t] = v0 + v1 + v2 + v3;
    __syncthreads();
    for (int o = 128; o > 0; o >>= 1) {
        if (t < o) red[t] += red[t + o];
        __syncthreads();
    }
    float mu = red[0] * (1.f / 1024.f);
    __syncthreads();
    float d0 = v0 - mu, d1 = v1 - mu, d2 = v2 - mu, d3 = v3 - mu;
    red[t] = d0 * d0 + d1 * d1 + d2 * d2 + d3 * d3;
    __syncthreads();
    for (int o = 128; o > 0; o >>= 1) {
        if (t < o) red[t] += red[t + o];
        __syncthreads();
    }
    float inv = rsqrtf(red[0] * (1.f / 1024.f) + EPSV);
    float4 gv = *(const float4*)(gam + c);
    float4 bv = *(const float4*)(bet + c);
    float y0 = d0 * inv * gv.x + bv.x;
    float y1 = d1 * inv * gv.y + bv.y;
    float y2 = d2 * inv * gv.z + bv.z;
    float y3 = d3 * inv * gv.w + bv.w;
    *(float4*)(out + (size_t)r * D + c) = make_float4(y0, y1, y2, y3);
    __half2 h01 = __floats2half2_rn(y0, y1);
    __half2 h23 = __floats2half2_rn(y2, y3);
    *(__half2*)(oh + (size_t)r * D + c)     = h01;
    *(__half2*)(oh + (size_t)r * D + c + 2) = h23;
}

__global__ void __launch_bounds__(256)
k_ln2(const float* __restrict__ xa, const float* __restrict__ p0,
      const float* __restrict__ p1, const float* __restrict__ b2,
      const float* __restrict__ gam, const float* __restrict__ bet,
      float* __restrict__ out) {
    int r = blockIdx.x, t = threadIdx.x;
    int c = t * 4;
    float4 a4 = *(const float4*)(xa + (size_t)r * D + c);
    float4 q0 = *(const float4*)(p0 + (size_t)r * D + c);
    float4 q1 = *(const float4*)(p1 + (size_t)r * D + c);
    float4 bb = *(const float4*)(b2 + c);
    float v0 = a4.x + (q0.x + q1.x + bb.x);
    float v1 = a4.y + (q0.y + q1.y + bb.y);
    float v2 = a4.z + (q0.z + q1.z + bb.z);
    float v3 = a4.w + (q0.w + q1.w + bb.w);
    __shared__ float red[256];
    red[t] = v0 + v1 + v2 + v3;
    __syncthreads();
    for (int o = 128; o > 0; o >>= 1) {
        if (t < o) red[t] += red[t + o];
        __syncthreads();
    }
    float mu = red[0] * (1.f / 1024.f);
    __syncthreads();
    float d0 = v0 - mu, d1 = v1 - mu, d2 = v2 - mu, d3 = v3 - mu;
    red[t] = d0 * d0 + d1 * d1 + d2 * d2 + d3 * d3;
    __syncthreads();
    for (int o = 128; o > 0; o >>= 1) {
        if (t < o) red[t] += red[t + o];
        __syncthreads();
    }
    float inv = rsqrtf(red[0] * (1.f / 1024.f) + EPSV);
    float4 gv = *(const float4*)(gam + c);
    float4 bv = *(const float4*)(bet + c);
    *(float4*)(out + (size_t)r * D + c) = make_float4(
        d0 * inv * gv.x + bv.x, d1 * inv * gv.y + bv.y,
        d2 * inv * gv.z + bv.z, d3 * inv * gv.w + bv.w);
}

// ------------------- launch ---------------------------------------------------
extern "C" void kernel_launch(void* const* d_in, const int* in_sizes, int n_in,
                              void* d_out, int out_size) {
    const float* x    = (const float*)d_in[0];
    const float* wq   = (const float*)d_in[1];
    const float* wk   = (const float*)d_in[2];
    const float* wv   = (const float*)d_in[3];
    const float* rel  = (const float*)d_in[4];
    const float* w1   = (const float*)d_in[5];
    const float* b1   = (const float*)d_in[6];
    const float* w2   = (const float*)d_in[7];
    const float* b2   = (const float*)d_in[8];
    const float* ln1g = (const float*)d_in[9];
    const float* ln1b = (const float*)d_in[10];
    const float* ln2g = (const float*)d_in[11];
    const float* ln2b = (const float*)d_in[12];
    float* out = (float*)d_out;

    cudaFuncSetAttribute(mma_gemm<1>, cudaFuncAttributeMaxDynamicSharedMemorySize, GEMM_SMEM);
    cudaFuncSetAttribute(mma_gemm<3>, cudaFuncAttributeMaxDynamicSharedMemorySize, GEMM_SMEM);

    float *pH1, *pFfn;
    __half *pH1h, *pMh, *pW1, *pW2;
    cudaGetSymbolAddress((void**)&pH1,   g_h1);
    cudaGetSymbolAddress((void**)&pFfn,  g_ffn);
    cudaGetSymbolAddress((void**)&pH1h,  g_h1h);
    cudaGetSymbolAddress((void**)&pMh,   g_midh);
    cudaGetSymbolAddress((void**)&pW1,   g_W1T);
    cudaGetSymbolAddress((void**)&pW2,   g_W2T);

    // weight transposes (fp16)
    k_trsp<<<dim3(DFF / 32, D / 32), 256>>>(w1, pW1, D, DFF);
    k_trsp<<<dim3(D / 32, DFF / 32), 256>>>(w2, pW2, DFF, D);

    // reduced Q,K path
    k_wsum<<<(D * H + 255) / 256, 256>>>(wq, wk);
    k_qskts<<<R, 256>>>(x);

    // rel_w reductions -> A2, SA1, extremes
    k_relw<<<dim3(S / 2, BH), 256>>>(rel);
    k_finalize<<<BH, 256>>>();

    // only the V rows the one-hot gather needs
    k_vsel<<<dim3(2, BH), 256>>>(x, wv);

    // exact softmax fallback for non-one-hot rows (early-exits; writes g_attn)
    k_attn_fb<<<dim3(S / 16, BH), 64>>>(x, wv);

    // LN1 with fused attention gather (+ fp16 h1)
    k_ln1<<<R, 256>>>(x, ln1g, ln1b, pH1, pH1h);

    // FFN GEMM1: mid = relu(h1 @ w1 + b1) -> fp16
    mma_gemm<1><<<dim3(DFF / 128, R / 128, 1), 256, GEMM_SMEM>>>(
        pH1h, pW1, b1, nullptr, pMh, R, DFF, D, D);

    // FFN GEMM2: split-K=2 partials (no bias)
    mma_gemm<3><<<dim3(D / 128, R / 128, 2), 256, GEMM_SMEM>>>(
        pMh, pW2, nullptr, pFfn, nullptr, R, D, DFF, DFF / 2);

    // LN2: LN(h1 + p0 + p1 + b2) -> output
    k_ln2<<<R, 256>>>(pH1, pFfn, pFfn + (size_t)R * D, b2, ln2g, ln2b, out);
}

// round 17
// speedup vs baseline: 1.0400x; 1.0400x over previous
#include <cuda_runtime.h>
#include <cuda_fp16.h>
#include <math.h>
#include <float.h>
#include <stdint.h>

static constexpr int S = 1024;
static constexpr int Bd = 2;
static constexpr int D = 1024;
static constexpr int H = 16;
static constexpr int DEPTH = 64;
static constexpr int DFF = 4096;
static constexpr int R = S * Bd;
static constexpr int BH = Bd * H;
static constexpr float SCALE = 0.125f;
static constexpr float NEGV = -1000000000.0f;
static constexpr float EPSV = 1e-5f;

// ------------------- scratch -------------------------------------------------
__device__ float g_attn[R * D];
__device__ float g_h1[R * D];
__device__ float g_ffn[2 * R * D];   // split-K partials (z = 0,1)
__device__ float2 g_wqk[D * H];      // interleaved (wqsum, wksum)
__device__ float g_qsT[BH * S];
__device__ float g_ktsT[BH * S];
__device__ float g_A2[BH * S];
__device__ float g_P1[BH * S];
__device__ float g_SA1[BH];
__device__ float g_mx[BH];
__device__ float g_mn[BH];
__device__ float g_mx2[BH];
__device__ float g_mn2[BH];
__device__ int   g_kmx[BH];
__device__ int   g_kmn[BH];
__device__ float g_Vsel[BH * 2 * DEPTH];
// fp16 operands
__device__ __half g_h1h[R * D];
__device__ __half g_midh[R * DFF];
__device__ __half g_W1T[DFF * D];
__device__ __half g_W2T[D * DFF];

// ------------------- PTX helpers ---------------------------------------------
__device__ __forceinline__ uint32_t smem_to_u32(const void* p) {
    uint32_t a;
    asm("{ .reg .u64 t; cvta.to.shared.u64 t, %1; cvt.u32.u64 %0, t; }" : "=r"(a) : "l"(p));
    return a;
}
__device__ __forceinline__ void ldsm4(uint32_t* r, uint32_t addr) {
    asm volatile("ldmatrix.sync.aligned.m8n8.x4.shared.b16 {%0,%1,%2,%3}, [%4];"
        : "=r"(r[0]), "=r"(r[1]), "=r"(r[2]), "=r"(r[3]) : "r"(addr));
}
__device__ __forceinline__ void mma16816(float* d, const uint32_t* a, const uint32_t* b) {
    asm volatile(
        "mma.sync.aligned.m16n8k16.row.col.f32.f16.f16.f32 "
        "{%0,%1,%2,%3}, {%4,%5,%6,%7}, {%8,%9}, {%0,%1,%2,%3};"
        : "+f"(d[0]), "+f"(d[1]), "+f"(d[2]), "+f"(d[3])
        : "r"(a[0]), "r"(a[1]), "r"(a[2]), "r"(a[3]), "r"(b[0]), "r"(b[1]));
}
__device__ __forceinline__ void cpasync16(uint32_t saddr, const void* gaddr) {
    asm volatile("cp.async.cg.shared.global [%0], [%1], 16;" :: "r"(saddr), "l"(gaddr));
}
#define CP_COMMIT() asm volatile("cp.async.commit_group;" ::: "memory")
#define CP_WAIT3()  asm volatile("cp.async.wait_group 3;" ::: "memory")
#define CP_WAIT2()  asm volatile("cp.async.wait_group 2;" ::: "memory")
#define CP_WAIT1()  asm volatile("cp.async.wait_group 1;" ::: "memory")
#define CP_WAIT0()  asm volatile("cp.async.wait_group 0;" ::: "memory")

// warp-shuffle block reduction: 256 threads, one barrier.
__device__ __forceinline__ float block_sum256(float v, float* red8, int t) {
#pragma unroll
    for (int o = 16; o > 0; o >>= 1) v += __shfl_xor_sync(0xFFFFFFFFu, v, o);
    if ((t & 31) == 0) red8[t >> 5] = v;
    __syncthreads();
    return red8[0] + red8[1] + red8[2] + red8[3]
         + red8[4] + red8[5] + red8[6] + red8[7];
}

// ------------------- K0: interleaved column-group sums of Wq, Wk -------------
__global__ void k_wsum(const float* __restrict__ wq, const float* __restrict__ wk) {
    int idx = blockIdx.x * blockDim.x + threadIdx.x;
    if (idx >= D * H) return;
    int k = idx / H, h = idx % H;
    const float* p1 = wq + (size_t)k * D + h * DEPTH;
    const float* p2 = wk + (size_t)k * D + h * DEPTH;
    float s1 = 0.f, s2 = 0.f;
#pragma unroll 16
    for (int d = 0; d < DEPTH; d++) { s1 += p1[d]; s2 += p2[d]; }
    g_wqk[k * H + h] = make_float2(s1, s2);
}

// ------------------- K1: qs / kts ---------------------------------------------
__global__ void k_qskts(const float* __restrict__ x) {
    int r = blockIdx.x;
    int t = threadIdx.x;
    __shared__ float sx[D];
    {
        float4 v = ((const float4*)(x + (size_t)r * D))[t];
        *(float4*)(sx + t * 4) = v;
    }
    __syncthreads();
    int h = t & 15, part = t >> 4;
    float a1 = 0.f, a2 = 0.f;
#pragma unroll 8
    for (int k = part; k < D; k += 16) {
        float xv = sx[k];
        float2 w = g_wqk[k * H + h];
        a1 = fmaf(xv, w.x, a1);
        a2 = fmaf(xv, w.y, a2);
    }
    __shared__ float s1[16][16];
    __shared__ float s2[16][16];
    s1[part][h] = a1; s2[part][h] = a2;
    __syncthreads();
    if (t < H) {
        float q = 0.f, kk = 0.f;
#pragma unroll
        for (int p = 0; p < 16; p++) { q += s1[p][t]; kk += s2[p][t]; }
        int b = r >> 10, s = r & 1023;
        g_qsT[(b * H + t) * S + s]  = SCALE * q;
        g_ktsT[(b * H + t) * S + s] = kk;
    }
}

// ------------------- transpose: W[Kd][Nd] -> WT fp16 [Nd][Kd] -----------------
__global__ void k_trsp(const float* __restrict__ W, __half* __restrict__ T,
                       int Kd, int Nd) {
    __shared__ float tile[32][33];
    int n0 = blockIdx.x * 32, k0 = blockIdx.y * 32;
    int c = threadIdx.x & 31, rq = threadIdx.x >> 5;
#pragma unroll
    for (int q = 0; q < 4; q++) {
        int kr = rq + q * 8;
        tile[kr][c] = W[(size_t)(k0 + kr) * Nd + n0 + c];
    }
    __syncthreads();
#pragma unroll
    for (int q = 0; q < 4; q++) {
        int nr = rq + q * 8;
        T[(size_t)(n0 + nr) * Kd + k0 + c] = __float2half_rn(tile[c][nr]);
    }
}

// ------------------- single-pass fp16 GEMM via mma.sync -----------------------
static constexpr int ROWB = 80;
static constexpr int TILEB = 128 * ROWB;
static constexpr int BUFB = 2 * TILEB;
static constexpr int NSTAGE = 4;
static constexpr int GEMM_SMEM = NSTAGE * BUFB;

template <int EPI>   // 1: bias+relu -> Ch fp16 ; 3: split-K partial -> fp32
__global__ void __launch_bounds__(256, 2)
mma_gemm(const __half* __restrict__ A, const __half* __restrict__ B,
         const float* __restrict__ bias, float* __restrict__ C,
         __half* __restrict__ Ch,
         int M, int N, int Ktot, int Ksl) {
    extern __shared__ char smem[];
    const uint32_t sbase = smem_to_u32(smem);
    int t = threadIdx.x;
    int lane = t & 31, wid = t >> 5;
    int wm = wid >> 2, wn = wid & 3;
    int m0 = blockIdx.y * 128, n0 = blockIdx.x * 128;
    const int kbase = blockIdx.z * Ksl;

    int lr = t >> 1, lh = t & 1;
    const __half* gsrc[2] = {
        A + (size_t)(m0 + lr) * Ktot + kbase + lh * 16,
        B + (size_t)(n0 + lr) * Ktot + kbase + lh * 16 };
    const uint32_t sdst = sbase + (uint32_t)(lr * ROWB + lh * 32);

    uint32_t aoff = (uint32_t)((wm * 64 + ((lane >> 3) & 1) * 8 + (lane & 7)) * ROWB
                               + ((lane >> 4) & 1) * 16);
    uint32_t boff = (uint32_t)((wn * 32 + ((lane >> 4) & 1) * 8 + (lane & 7)) * ROWB
                               + ((lane >> 3) & 1) * 16);

    float acc[4][4][4];
#pragma unroll
    for (int i = 0; i < 4; i++)
#pragma unroll
        for (int j = 0; j < 4; j++)
#pragma unroll
            for (int e = 0; e < 4; e++) acc[i][j][e] = 0.f;

#define ISSUE(chunk, buf) do { \
    uint32_t _db = sdst + (uint32_t)(buf) * BUFB; \
    size_t _go = (size_t)(chunk) * 32; \
    _Pragma("unroll") \
    for (int _tl = 0; _tl < 2; _tl++) { \
        const __half* _g = gsrc[_tl] + _go; \
        cpasync16(_db + _tl * TILEB,      _g); \
        cpasync16(_db + _tl * TILEB + 16, _g + 8); \
    } } while (0)

    const int NC = Ksl >> 5;
    ISSUE(0, 0); CP_COMMIT();
    ISSUE(1, 1); CP_COMMIT();
    ISSUE(2, 2); CP_COMMIT();

    int buf = 0;
    for (int c = 0; c < NC; c++) {
        if (c + 3 < NC) {
            int nb = buf + 3; if (nb >= NSTAGE) nb -= NSTAGE;
            ISSUE(c + 3, nb); CP_COMMIT(); CP_WAIT3();
        } else if (c + 2 < NC) {
            CP_WAIT2();
        } else if (c + 1 < NC) {
            CP_WAIT1();
        } else {
            CP_WAIT0();
        }
        __syncthreads();
        uint32_t bb = sbase + (uint32_t)buf * BUFB;
#pragma unroll
        for (int s = 0; s < 2; s++) {
            uint32_t Ah[4][4], Bh[2][4];
#pragma unroll
            for (int i = 0; i < 4; i++)
                ldsm4(Ah[i], bb + aoff + i * 16 * ROWB + s * 32);
#pragma unroll
            for (int j2 = 0; j2 < 2; j2++)
                ldsm4(Bh[j2], bb + TILEB + boff + j2 * 16 * ROWB + s * 32);
#pragma unroll
            for (int i = 0; i < 4; i++)
#pragma unroll
                for (int j = 0; j < 4; j++)
                    mma16816(acc[i][j], Ah[i], &Bh[j >> 1][(j & 1) * 2]);
        }
        __syncthreads();
        if (++buf == NSTAGE) buf = 0;
    }
#undef ISSUE

    int r0 = lane >> 2, c2 = (lane & 3) * 2;
    float* Cz = C;
    if constexpr (EPI == 3) Cz = C + (size_t)blockIdx.z * M * N;
#pragma unroll
    for (int i = 0; i < 4; i++) {
#pragma unroll
        for (int j = 0; j < 4; j++) {
            int m = m0 + wm * 64 + i * 16 + r0;
            int n = n0 + wn * 32 + j * 8 + c2;
            float v0 = acc[i][j][0], v1 = acc[i][j][1];
            float v2 = acc[i][j][2], v3 = acc[i][j][3];
            if constexpr (EPI == 1) {
                float b0 = bias[n], b1 = bias[n + 1];
                v0 = fmaxf(v0 + b0, 0.f); v1 = fmaxf(v1 + b1, 0.f);
                v2 = fmaxf(v2 + b0, 0.f); v3 = fmaxf(v3 + b1, 0.f);
                *(__half2*)(Ch + (size_t)m * N + n)       = __floats2half2_rn(v0, v1);
                *(__half2*)(Ch + (size_t)(m + 8) * N + n) = __floats2half2_rn(v2, v3);
            } else {
                *(float2*)(Cz + (size_t)m * N + n)       = make_float2(v0, v1);
                *(float2*)(Cz + (size_t)(m + 8) * N + n) = make_float2(v2, v3);
            }
        }
    }
}

// ------------------- K3: rel_w reductions (R15 form + shuffle reduction) ------
__global__ void k_relw(const float* __restrict__ rel) {
    int p = blockIdx.x;
    int bh = blockIdx.y;
    int t = threadIdx.x;
    const float* kts = g_ktsT + bh * S;
    int ks[2] = { p, 1023 - p };
    float res[4];
#pragma unroll
    for (int rr = 0; rr < 2; rr++) {
        int k = ks[rr];
        const float* base = rel + ((size_t)bh * S + k) * S + (1023 - k);
        int len = k + 1;
        int head = (4 - ((1023 - k) & 3)) & 3;
        if (head > len) head = len;
        float a1 = 0.f, a2 = 0.f;
        if (t < head) {
            float rv = base[t], kv = kts[t];
            a1 += kv * rv;
            a2 += (kv + NEGV * (float)t) * rv;
        }
        int nvec = (len - head) >> 2;
        for (int i = t; i < nvec; i += 256) {
            int m0 = head + i * 4;
            float4 rv = *(const float4*)(base + m0);
            float kv0 = kts[m0], kv1 = kts[m0 + 1], kv2 = kts[m0 + 2], kv3 = kts[m0 + 3];
            a1 += kv0 * rv.x + kv1 * rv.y + kv2 * rv.z + kv3 * rv.w;
            float w0 = kv0 + NEGV * (float)min(m0, 64);
            float w1 = kv1 + NEGV * (float)min(m0 + 1, 64);
            float w2 = kv2 + NEGV * (float)min(m0 + 2, 64);
            float w3 = kv3 + NEGV * (float)min(m0 + 3, 64);
            a2 += w0 * rv.x + w1 * rv.y + w2 * rv.z + w3 * rv.w;
        }
        for (int m = head + nvec * 4 + t; m < len; m += 256) {
            float rv = base[m], kv = kts[m];
            a1 += kv * rv;
            a2 += (kv + NEGV * (float)min(m, 64)) * rv;
        }
        res[rr * 2] = a1; res[rr * 2 + 1] = a2;
    }
    // shuffle reduce 4 values, then 8-slot smem, one barrier
    __shared__ float4 red8[8];
#pragma unroll
    for (int o = 16; o > 0; o >>= 1) {
        res[0] += __shfl_xor_sync(0xFFFFFFFFu, res[0], o);
        res[1] += __shfl_xor_sync(0xFFFFFFFFu, res[1], o);
        res[2] += __shfl_xor_sync(0xFFFFFFFFu, res[2], o);
        res[3] += __shfl_xor_sync(0xFFFFFFFFu, res[3], o);
    }
    if ((t & 31) == 0) red8[t >> 5] = make_float4(res[0], res[1], res[2], res[3]);
    __syncthreads();
    if (t == 0) {
        float4 v = red8[0];
#pragma unroll
        for (int w = 1; w < 8; w++) {
            float4 u = red8[w];
            v.x += u.x; v.y += u.y; v.z += u.z; v.w += u.w;
        }
        g_P1[bh * S + ks[0]] = v.x;
        g_A2[bh * S + ks[0]] = v.y;
        g_P1[bh * S + ks[1]] = v.z;
        g_A2[bh * S + ks[1]] = v.w;
    }
}

// ------------------- K4: SA1 + top-2 extremes per bh -------------------------
__global__ void k_finalize() {
    int bh = blockIdx.x, t = threadIdx.x;
    __shared__ float ss[256];
    __shared__ float sv[256];
    __shared__ int   si[256];
    __shared__ float sw_[256];
    __shared__ int   sj[256];
    const float* A2 = g_A2 + bh * S;
    float sa = 0.f, mx = -FLT_MAX, mn = FLT_MAX;
    int im = 0, imn = 0;
    for (int k = t; k < S; k += 256) {
        sa += g_P1[bh * S + k];
        float a = A2[k];
        if (a > mx) { mx = a; im = k; }
        if (a < mn) { mn = a; imn = k; }
    }
    ss[t] = sa; sv[t] = mx; si[t] = im; sw_[t] = mn; sj[t] = imn;
    __syncthreads();
    for (int o = 128; o > 0; o >>= 1) {
        if (t < o) {
            ss[t] += ss[t + o];
            if (sv[t + o] > sv[t]) { sv[t] = sv[t + o]; si[t] = si[t + o]; }
            if (sw_[t + o] < sw_[t]) { sw_[t] = sw_[t + o]; sj[t] = sj[t + o]; }
        }
        __syncthreads();
    }
    int kmx = si[0], kmn = sj[0];
    float vmx = sv[0], vmn = sw_[0], vsa = ss[0];
    __syncthreads();
    float mx2 = -FLT_MAX, mn2 = FLT_MAX;
    for (int k = t; k < S; k += 256) {
        float a = A2[k];
        if (k != kmx && a > mx2) mx2 = a;
        if (k != kmn && a < mn2) mn2 = a;
    }
    sv[t] = mx2; sw_[t] = mn2;
    __syncthreads();
    for (int o = 128; o > 0; o >>= 1) {
        if (t < o) { sv[t] = fmaxf(sv[t], sv[t + o]); sw_[t] = fminf(sw_[t], sw_[t + o]); }
        __syncthreads();
    }
    if (t == 0) {
        g_SA1[bh] = vsa;
        g_mx[bh] = vmx; g_mn[bh] = vmn;
        g_mx2[bh] = sv[0]; g_mn2[bh] = sw_[0];
        g_kmx[bh] = kmx; g_kmn[bh] = kmn;
    }
}

// ------------------- K4b: compute ONLY the V rows the gather needs -----------
__global__ void k_vsel(const float* __restrict__ x, const float* __restrict__ wv) {
    int sel = blockIdx.x;
    int bh = blockIdx.y;
    int b = bh >> 4, h = bh & 15;
    int krow = sel ? g_kmn[bh] : g_kmx[bh];
    int t = threadIdx.x;
    int n = t & 63, part = t >> 6;
    const float* xr = x + ((size_t)b * S + krow) * D;
    const float* wc = wv + (size_t)h * DEPTH + n;
    float s = 0.f;
    for (int k = part * 256; k < part * 256 + 256; k++)
        s = fmaf(xr[k], wc[(size_t)k * D], s);
    __shared__ float red[4][64];
    red[part][n] = s;
    __syncthreads();
    if (t < 64)
        g_Vsel[(bh * 2 + sel) * DEPTH + t] =
            red[0][t] + red[1][t] + red[2][t] + red[3][t];
}

// ------------------- sel decision ---------------------------------------------
__device__ __forceinline__ int attn_sel(int bh, int j, float& cj_out) {
    float cj = SCALE * g_qsT[bh * S + j] * g_SA1[bh];
    cj_out = cj;
    if (cj > 0.f      && cj * (g_mx[bh] - g_mx2[bh]) > 90.f)    return 0;
    if (cj < 0.f && (-cj) * (g_mn2[bh] - g_mn[bh]) > 90.f)      return 1;
    return -1;
}

// ------------------- K5b: exact softmax fallback (16-row scan, early exit) ----
__global__ void __launch_bounds__(64)
k_attn_fb(const float* __restrict__ x, const float* __restrict__ wv) {
    int bh = blockIdx.y;
    int b = bh >> 4, h = bh & 15;
    int lane = threadIdx.x;
    for (int jj = 0; jj < 16; jj++) {
        int j = blockIdx.x * 16 + jj;
        float cj;
        if (attn_sel(bh, j, cj) >= 0) continue;
        float mj = (cj >= 0.f) ? cj * g_mx[bh] : cj * g_mn[bh];
        const float* A2 = g_A2 + bh * S;
        float den = 0.f, acc = 0.f;
        for (int k = 0; k < S; k++) {
            float e = __expf(fminf(cj * A2[k] - mj, 0.f));
            den += e;
            if (e > 0.f) {
                const float* xr = x + ((size_t)b * S + k) * D;
                const float* w = wv + (size_t)h * DEPTH + lane;
                float vv = 0.f;
                for (int kk = 0; kk < D; kk++)
                    vv = fmaf(xr[kk], w[(size_t)kk * D], vv);
                acc = fmaf(e, vv, acc);
            }
        }
        g_attn[((size_t)bh * S + j) * DEPTH + lane] = acc / den;
    }
}

// ------------------- LN kernels (shuffle reductions) ---------------------------
__global__ void __launch_bounds__(256)
k_ln1(const float* __restrict__ xa,
      const float* __restrict__ gam, const float* __restrict__ bet,
      float* __restrict__ out, __half* __restrict__ oh) {
    int r = blockIdx.x, t = threadIdx.x;
    int c = t * 4;
    int bh = r >> 6;
    int j = (r & 63) * 16 + (c >> 6);
    int n = c & 63;
    float cj;
    int sel = attn_sel(bh, j, cj);
    float4 av;
    if (sel >= 0) av = *(const float4*)(g_Vsel + (bh * 2 + sel) * DEPTH + n);
    else          av = *(const float4*)(g_attn + (size_t)r * D + c);

    float4 xv = *(const float4*)(xa + (size_t)r * D + c);
    float v0 = xv.x + av.x, v1 = xv.y + av.y, v2 = xv.z + av.z, v3 = xv.w + av.w;

    __shared__ float redA[8];
    __shared__ float redB[8];
    float mu = block_sum256(v0 + v1 + v2 + v3, redA, t) * (1.f / 1024.f);
    float d0 = v0 - mu, d1 = v1 - mu, d2 = v2 - mu, d3 = v3 - mu;
    float s2 = block_sum256(d0 * d0 + d1 * d1 + d2 * d2 + d3 * d3, redB, t);
    float inv = rsqrtf(s2 * (1.f / 1024.f) + EPSV);
    float4 gv = *(const float4*)(gam + c);
    float4 bv = *(const float4*)(bet + c);
    float y0 = d0 * inv * gv.x + bv.x;
    float y1 = d1 * inv * gv.y + bv.y;
    float y2 = d2 * inv * gv.z + bv.z;
    float y3 = d3 * inv * gv.w + bv.w;
    *(float4*)(out + (size_t)r * D + c) = make_float4(y0, y1, y2, y3);
    *(__half2*)(oh + (size_t)r * D + c)     = __floats2half2_rn(y0, y1);
    *(__half2*)(oh + (size_t)r * D + c + 2) = __floats2half2_rn(y2, y3);
}

__global__ void __launch_bounds__(256)
k_ln2(const float* __restrict__ xa, const float* __restrict__ p0,
      const float* __restrict__ p1, const float* __restrict__ b2,
      const float* __restrict__ gam, const float* __restrict__ bet,
      float* __restrict__ out) {
    int r = blockIdx.x, t = threadIdx.x;
    int c = t * 4;
    float4 a4 = *(const float4*)(xa + (size_t)r * D + c);
    float4 q0 = *(const float4*)(p0 + (size_t)r * D + c);
    float4 q1 = *(const float4*)(p1 + (size_t)r * D + c);
    float4 bb = *(const float4*)(b2 + c);
    float v0 = a4.x + (q0.x + q1.x + bb.x);
    float v1 = a4.y + (q0.y + q1.y + bb.y);
    float v2 = a4.z + (q0.z + q1.z + bb.z);
    float v3 = a4.w + (q0.w + q1.w + bb.w);
    __shared__ float redA[8];
    __shared__ float redB[8];
    float mu = block_sum256(v0 + v1 + v2 + v3, redA, t) * (1.f / 1024.f);
    float d0 = v0 - mu, d1 = v1 - mu, d2 = v2 - mu, d3 = v3 - mu;
    float s2 = block_sum256(d0 * d0 + d1 * d1 + d2 * d2 + d3 * d3, redB, t);
    float inv = rsqrtf(s2 * (1.f / 1024.f) + EPSV);
    float4 gv = *(const float4*)(gam + c);
    float4 bv = *(const float4*)(bet + c);
    *(float4*)(out + (size_t)r * D + c) = make_float4(
        d0 * inv * gv.x + bv.x, d1 * inv * gv.y + bv.y,
        d2 * inv * gv.z + bv.z, d3 * inv * gv.w + bv.w);
}

// ------------------- launch ---------------------------------------------------
extern "C" void kernel_launch(void* const* d_in, const int* in_sizes, int n_in,
                              void* d_out, int out_size) {
    const float* x    = (const float*)d_in[0];
    const float* wq   = (const float*)d_in[1];
    const float* wk   = (const float*)d_in[2];
    const float* wv   = (const float*)d_in[3];
    const float* rel  = (const float*)d_in[4];
    const float* w1   = (const float*)d_in[5];
    const float* b1   = (const float*)d_in[6];
    const float* w2   = (const float*)d_in[7];
    const float* b2   = (const float*)d_in[8];
    const float* ln1g = (const float*)d_in[9];
    const float* ln1b = (const float*)d_in[10];
    const float* ln2g = (const float*)d_in[11];
    const float* ln2b = (const float*)d_in[12];
    float* out = (float*)d_out;

    cudaFuncSetAttribute(mma_gemm<1>, cudaFuncAttributeMaxDynamicSharedMemorySize, GEMM_SMEM);
    cudaFuncSetAttribute(mma_gemm<3>, cudaFuncAttributeMaxDynamicSharedMemorySize, GEMM_SMEM);

    float *pH1, *pFfn;
    __half *pH1h, *pMh, *pW1, *pW2;
    cudaGetSymbolAddress((void**)&pH1,   g_h1);
    cudaGetSymbolAddress((void**)&pFfn,  g_ffn);
    cudaGetSymbolAddress((void**)&pH1h,  g_h1h);
    cudaGetSymbolAddress((void**)&pMh,   g_midh);
    cudaGetSymbolAddress((void**)&pW1,   g_W1T);
    cudaGetSymbolAddress((void**)&pW2,   g_W2T);

    // weight transposes (fp16)
    k_trsp<<<dim3(DFF / 32, D / 32), 256>>>(w1, pW1, D, DFF);
    k_trsp<<<dim3(D / 32, DFF / 32), 256>>>(w2, pW2, DFF, D);

    // reduced Q,K path
    k_wsum<<<(D * H + 255) / 256, 256>>>(wq, wk);
    k_qskts<<<R, 256>>>(x);

    // rel_w reductions -> A2, SA1, extremes
    k_relw<<<dim3(S / 2, BH), 256>>>(rel);
    k_finalize<<<BH, 256>>>();

    // only the V rows the one-hot gather needs
    k_vsel<<<dim3(2, BH), 256>>>(x, wv);

    // exact softmax fallback for non-one-hot rows (early-exits; writes g_attn)
    k_attn_fb<<<dim3(S / 16, BH), 64>>>(x, wv);

    // LN1 with fused attention gather (+ fp16 h1)
    k_ln1<<<R, 256>>>(x, ln1g, ln1b, pH1, pH1h);

    // FFN GEMM1: mid = relu(h1 @ w1 + b1) -> fp16
    mma_gemm<1><<<dim3(DFF / 128, R / 128, 1), 256, GEMM_SMEM>>>(
        pH1h, pW1, b1, nullptr, pMh, R, DFF, D, D);

    // FFN GEMM2: split-K=2 partials (no bias)
    mma_gemm<3><<<dim3(D / 128, R / 128, 2), 256, GEMM_SMEM>>>(
        pMh, pW2, nullptr, pFfn, nullptr, R, D, DFF, DFF / 2);

    // LN2: LN(h1 + p0 + p1 + b2) -> output
    k_ln2<<<R, 256>>>(pH1, pFfn, pFfn + (size_t)R * D, b2, ln2g, ln2b, out);
}